// round 2
// baseline (speedup 1.0000x reference)
#include <cuda_runtime.h>

#define HD 128
#define DD 8

// Precomputed trace matrix M[k][j] = W2[k][j] * sum_d W1[d][k]*W3[j][d]
__device__ float g_M[HD * HD];

__device__ __forceinline__ float fast_tanh(float x) {
    float y;
    asm("tanh.approx.f32 %0, %1;" : "=f"(y) : "f"(x));
    return y;
}

__global__ void precompute_M_kernel(const float* __restrict__ W1,
                                    const float* __restrict__ W2,
                                    const float* __restrict__ W3) {
    int idx = blockIdx.x * blockDim.x + threadIdx.x;
    if (idx >= HD * HD) return;
    int k = idx >> 7;
    int j = idx & (HD - 1);
    float c = 0.0f;
#pragma unroll
    for (int d = 0; d < DD; d++)
        c += W1[d * HD + k] * W3[j * DD + d];
    g_M[idx] = W2[idx] * c;
}

// smem (floats): W2s[16384] | Ms[16384] | W1s[9*128] | W3s[128*8] | b1s[128] | b2s[128] | b3s[8]
#define SMEM_FLOATS (2 * HD * HD + 9 * HD + HD * DD + HD + HD + DD)
#define SMEM_BYTES  (SMEM_FLOATS * 4)

#define TPB 256

__global__ __launch_bounds__(TPB, 1)
void cnf_kernel(const float* __restrict__ z,
                const float* __restrict__ t,
                const float* __restrict__ W1, const float* __restrict__ b1,
                const float* __restrict__ W2, const float* __restrict__ b2,
                const float* __restrict__ W3, const float* __restrict__ b3,
                float* __restrict__ dz_out, float* __restrict__ dlogp_out,
                int B)
{
    extern __shared__ float sm[];
    float* W2s = sm;                  // [k][j] row-major
    float* Ms  = W2s + HD * HD;       // [k][j] row-major
    float* W1s = Ms  + HD * HD;       // [d][k], d = 0..8 (row 8 = t row)
    float* W3s = W1s + 9 * HD;        // [j][d]
    float* b1s = W3s + HD * DD;
    float* b2s = b1s + HD;
    float* b3s = b2s + HD;

    const int tid = threadIdx.x;

    for (int i = tid; i < HD * HD; i += TPB) {
        W2s[i] = W2[i];
        Ms[i]  = g_M[i];
    }
    for (int i = tid; i < 9 * HD; i += TPB) W1s[i] = W1[i];
    for (int i = tid; i < HD * DD; i += TPB) W3s[i] = W3[i];
    if (tid < HD) { b1s[tid] = b1[tid]; b2s[tid] = b2[tid]; }
    if (tid < DD) b3s[tid] = b3[tid];
    __syncthreads();

    const int sample = blockIdx.x * TPB + tid;
    if (sample >= B) return;

    // ---- load z sample ----
    float zr[DD];
    const float4* zv = (const float4*)(z + (size_t)sample * DD);
    float4 za = zv[0], zb = zv[1];
    zr[0] = za.x; zr[1] = za.y; zr[2] = za.z; zr[3] = za.w;
    zr[4] = zb.x; zr[5] = zb.y; zr[6] = zb.z; zr[7] = zb.w;
    const float tv = t[0];

    // ---- layer 1: h1 = tanh(z @ W1[0:8] + t*W1[8] + b1), in registers ----
    float h1[HD];
#pragma unroll
    for (int k = 0; k < HD; k += 4) {
        float4 acc = *(const float4*)&b1s[k];
#pragma unroll
        for (int d = 0; d < DD; d++) {
            float4 w = *(const float4*)&W1s[d * HD + k];
            acc.x += zr[d] * w.x; acc.y += zr[d] * w.y;
            acc.z += zr[d] * w.z; acc.w += zr[d] * w.w;
        }
        float4 w8 = *(const float4*)&W1s[8 * HD + k];
        acc.x += tv * w8.x; acc.y += tv * w8.y;
        acc.z += tv * w8.z; acc.w += tv * w8.w;
        h1[k + 0] = fast_tanh(acc.x);
        h1[k + 1] = fast_tanh(acc.y);
        h1[k + 2] = fast_tanh(acc.z);
        h1[k + 3] = fast_tanh(acc.w);
    }

    float dz[DD];
#pragma unroll
    for (int d = 0; d < DD; d++) dz[d] = b3s[d];

    float trace = 0.0f;

    // ---- fused pass: per j-tile compute a2[j] (W2) and u[j] (M) in one k-loop,
    //      then h2 = tanh(a2), dz += h2@W3, trace += u * (1 - h2^2) ----
#pragma unroll 1
    for (int jt = 0; jt < HD; jt += 8) {
        float a[8], u[8];
#pragma unroll
        for (int q = 0; q < 8; q++) { a[q] = b2s[jt + q]; u[q] = 0.0f; }
#pragma unroll
        for (int k = 0; k < HD; k++) {
            float hv = h1[k];
            float sv = fmaf(-hv, hv, 1.0f);   // s1[k] = 1 - h1^2, on the fly
            const float* w2row = &W2s[k * HD + jt];
            const float* mrow  = &Ms[k * HD + jt];
            float4 w0 = *(const float4*)(w2row);
            float4 w1 = *(const float4*)(w2row + 4);
            float4 m0 = *(const float4*)(mrow);
            float4 m1 = *(const float4*)(mrow + 4);
            a[0] += hv * w0.x; a[1] += hv * w0.y; a[2] += hv * w0.z; a[3] += hv * w0.w;
            a[4] += hv * w1.x; a[5] += hv * w1.y; a[6] += hv * w1.z; a[7] += hv * w1.w;
            u[0] += sv * m0.x; u[1] += sv * m0.y; u[2] += sv * m0.z; u[3] += sv * m0.w;
            u[4] += sv * m1.x; u[5] += sv * m1.y; u[6] += sv * m1.z; u[7] += sv * m1.w;
        }
#pragma unroll
        for (int q = 0; q < 8; q++) {
            float h2 = fast_tanh(a[q]);
            float s2 = fmaf(-h2, h2, 1.0f);
            trace = fmaf(u[q], s2, trace);
            float4 w3a = *(const float4*)&W3s[(jt + q) * DD + 0];
            float4 w3b = *(const float4*)&W3s[(jt + q) * DD + 4];
            dz[0] += h2 * w3a.x; dz[1] += h2 * w3a.y; dz[2] += h2 * w3a.z; dz[3] += h2 * w3a.w;
            dz[4] += h2 * w3b.x; dz[5] += h2 * w3b.y; dz[6] += h2 * w3b.z; dz[7] += h2 * w3b.w;
        }
    }

    // ---- outputs ----
    float4* outv = (float4*)(dz_out + (size_t)sample * DD);
    outv[0] = make_float4(dz[0], dz[1], dz[2], dz[3]);
    outv[1] = make_float4(dz[4], dz[5], dz[6], dz[7]);
    dlogp_out[sample] = -trace;
}

extern "C" void kernel_launch(void* const* d_in, const int* in_sizes, int n_in,
                              void* d_out, int out_size) {
    const float* z  = (const float*)d_in[0];
    // d_in[1] = logp_z (unused: dlogp/dt = -trace only)
    const float* t  = (const float*)d_in[2];
    const float* W1 = (const float*)d_in[3];
    const float* b1 = (const float*)d_in[4];
    const float* W2 = (const float*)d_in[5];
    const float* b2 = (const float*)d_in[6];
    const float* W3 = (const float*)d_in[7];
    const float* b3 = (const float*)d_in[8];

    const int B = in_sizes[0] / DD;
    float* dz_out    = (float*)d_out;
    float* dlogp_out = dz_out + (size_t)B * DD;

    precompute_M_kernel<<<(HD * HD + 255) / 256, 256>>>(W1, W2, W3);

    static int attr_set = 0;
    if (!attr_set) {
        cudaFuncSetAttribute(cnf_kernel,
                             cudaFuncAttributeMaxDynamicSharedMemorySize, SMEM_BYTES);
        attr_set = 1;
    }
    cnf_kernel<<<(B + TPB - 1) / TPB, TPB, SMEM_BYTES>>>(
        z, t, W1, b1, W2, b2, W3, b3, dz_out, dlogp_out, B);
}

// round 3
// speedup vs baseline: 2.1435x; 2.1435x over previous
#include <cuda_runtime.h>

#define HD 128
#define DD 8
#define TPB 256
#define SPB 128   // samples per block

typedef unsigned long long ull;

// Precomputed trace matrix M[k][j] = W2[k][j] * sum_d W1[d][k]*W3[j][d]
__device__ float g_M[HD * HD];

__device__ __forceinline__ float fast_tanh(float x) {
    float y;
    asm("tanh.approx.f32 %0, %1;" : "=f"(y) : "f"(x));
    return y;
}

__device__ __forceinline__ ull pack2(float a, float b) {
    ull r; asm("mov.b64 %0, {%1,%2};" : "=l"(r) : "f"(a), "f"(b)); return r;
}
__device__ __forceinline__ float2 unpack2(ull v) {
    float2 f; asm("mov.b64 {%0,%1}, %2;" : "=f"(f.x), "=f"(f.y) : "l"(v)); return f;
}
__device__ __forceinline__ ull fma2(ull a, ull b, ull c) {
    ull r; asm("fma.rn.f32x2 %0, %1, %2, %3;" : "=l"(r) : "l"(a), "l"(b), "l"(c)); return r;
}
__device__ __forceinline__ ull mul2(ull a, ull b) {
    ull r; asm("mul.rn.f32x2 %0, %1, %2;" : "=l"(r) : "l"(a), "l"(b)); return r;
}
__device__ __forceinline__ ull add2(ull a, ull b) {
    ull r; asm("add.rn.f32x2 %0, %1, %2;" : "=l"(r) : "l"(a), "l"(b)); return r;
}

__global__ void precompute_M_kernel(const float* __restrict__ W1,
                                    const float* __restrict__ W2,
                                    const float* __restrict__ W3) {
    int idx = blockIdx.x * blockDim.x + threadIdx.x;
    if (idx >= HD * HD) return;
    int k = idx >> 7;
    int j = idx & (HD - 1);
    float c = 0.0f;
#pragma unroll
    for (int d = 0; d < DD; d++)
        c += W1[d * HD + k] * W3[j * DD + d];
    g_M[idx] = W2[idx] * c;
}

// smem (floats): H1s[128*128] | W2s[128*128] | Ms[128*128] | W1s[9*128] | W3s[128*8] | b1s[128] | b2s[128] | b3s[8+pad] | css[128]
#define SMEM_FLOATS (3 * HD * HD + 9 * HD + HD * DD + HD + HD + 8 + HD)
#define SMEM_BYTES  (SMEM_FLOATS * 4)

__global__ __launch_bounds__(TPB, 1)
void cnf_kernel(const float* __restrict__ z,
                const float* __restrict__ t,
                const float* __restrict__ W1, const float* __restrict__ b1,
                const float* __restrict__ b2, const float* __restrict__ W3,
                const float* __restrict__ b3, const float* __restrict__ W2,
                float* __restrict__ dz_out, float* __restrict__ dlogp_out,
                int B)
{
    extern __shared__ float sm[];
    float* H1s = sm;                 // [k][s] 64 KB
    float* W2s = H1s + HD * HD;      // [k][j] 64 KB
    float* Ms  = W2s + HD * HD;      // [k][j] 64 KB
    float* W1s = Ms  + HD * HD;      // [d][k] d=0..8 (row 8 = t row)
    float* W3s = W1s + 9 * HD;       // [j][d]
    float* b1s = W3s + HD * DD;
    float* b2s = b1s + HD;
    float* b3s = b2s + HD;
    float* css = b3s + 8;            // column sums of M

    const int tid = threadIdx.x;

    // ---- stage weights ----
    for (int i = tid; i < HD * HD; i += TPB) {
        W2s[i] = W2[i];
        Ms[i]  = g_M[i];
    }
    for (int i = tid; i < 9 * HD; i += TPB) W1s[i] = W1[i];
    for (int i = tid; i < HD * DD; i += TPB) W3s[i] = W3[i];
    if (tid < HD) { b1s[tid] = b1[tid]; b2s[tid] = b2[tid]; }
    if (tid < DD) b3s[tid] = b3[tid];
    __syncthreads();

    // ---- colsum of M (per-CTA, cheap) ----
    if (tid < HD) {
        float c = 0.0f;
        for (int k = 0; k < HD; k++) c += Ms[k * HD + tid];
        css[tid] = c;
    }

    // ---- layer 1: H1s[k][s] = tanh(z@W1 + t*W1[8] + b1) ----
    {
        const int s_loc = tid & 127;
        const int kh = tid >> 7;               // 0 or 1 -> k half
        const int sample = blockIdx.x * SPB + s_loc;
        float zr[DD];
        const float4* zv = (const float4*)(z + (size_t)sample * DD);
        float4 za = zv[0], zb = zv[1];
        zr[0]=za.x; zr[1]=za.y; zr[2]=za.z; zr[3]=za.w;
        zr[4]=zb.x; zr[5]=zb.y; zr[6]=zb.z; zr[7]=zb.w;
        const float tv = t[0];
#pragma unroll 4
        for (int k0 = kh * 64; k0 < kh * 64 + 64; k0 += 4) {
            float4 acc = *(const float4*)&b1s[k0];
#pragma unroll
            for (int d = 0; d < DD; d++) {
                float4 w = *(const float4*)&W1s[d * HD + k0];
                acc.x = fmaf(zr[d], w.x, acc.x);
                acc.y = fmaf(zr[d], w.y, acc.y);
                acc.z = fmaf(zr[d], w.z, acc.z);
                acc.w = fmaf(zr[d], w.w, acc.w);
            }
            float4 w8 = *(const float4*)&W1s[8 * HD + k0];
            acc.x = fmaf(tv, w8.x, acc.x);
            acc.y = fmaf(tv, w8.y, acc.y);
            acc.z = fmaf(tv, w8.z, acc.z);
            acc.w = fmaf(tv, w8.w, acc.w);
            H1s[(k0 + 0) * HD + s_loc] = fast_tanh(acc.x);
            H1s[(k0 + 1) * HD + s_loc] = fast_tanh(acc.y);
            H1s[(k0 + 2) * HD + s_loc] = fast_tanh(acc.z);
            H1s[(k0 + 3) * HD + s_loc] = fast_tanh(acc.w);
        }
    }
    __syncthreads();

    // ---- GEMM phase: warp owns 16 samples; lane = (sg:2b, jg:3b) -> 4 samples x 4 j ----
    const int wid  = tid >> 5;
    const int lane = tid & 31;
    const int sg = lane & 3;
    const int jg = lane >> 2;
    const int sbase = wid * 16 + sg * 4;       // local sample base (4 samples)

    ull dzp[4][4];                             // [s][dpair], b3 added at the end
    float tr[4] = {0.f, 0.f, 0.f, 0.f};
#pragma unroll
    for (int s = 0; s < 4; s++)
#pragma unroll
        for (int dp = 0; dp < 4; dp++) dzp[s][dp] = 0ULL;

#pragma unroll 1
    for (int jt = 0; jt < HD; jt += 32) {
        const int j0 = jt + jg * 4;            // lane's j's: j0..j0+3 (two pairs)
        ull a[4][2], u[4][2];
        {
            ull b2p0 = *(const ull*)&b2s[j0];
            ull b2p1 = *(const ull*)&b2s[j0 + 2];
#pragma unroll
            for (int s = 0; s < 4; s++) {
                a[s][0] = b2p0; a[s][1] = b2p1;
                u[s][0] = 0ULL; u[s][1] = 0ULL;
            }
        }
#pragma unroll 2
        for (int k = 0; k < HD; k++) {
            float4 h4 = *(const float4*)&H1s[k * HD + sbase];
            ull hp0 = pack2(h4.x, h4.x);
            ull hp1 = pack2(h4.y, h4.y);
            ull hp2 = pack2(h4.z, h4.z);
            ull hp3 = pack2(h4.w, h4.w);
            ull q0 = mul2(hp0, hp0);
            ull q1 = mul2(hp1, hp1);
            ull q2 = mul2(hp2, hp2);
            ull q3 = mul2(hp3, hp3);
            ull w2p0 = *(const ull*)&W2s[k * HD + j0];
            ull w2p1 = *(const ull*)&W2s[k * HD + j0 + 2];
            ull mp0  = *(const ull*)&Ms[k * HD + j0];
            ull mp1  = *(const ull*)&Ms[k * HD + j0 + 2];
            a[0][0] = fma2(hp0, w2p0, a[0][0]);  a[0][1] = fma2(hp0, w2p1, a[0][1]);
            a[1][0] = fma2(hp1, w2p0, a[1][0]);  a[1][1] = fma2(hp1, w2p1, a[1][1]);
            a[2][0] = fma2(hp2, w2p0, a[2][0]);  a[2][1] = fma2(hp2, w2p1, a[2][1]);
            a[3][0] = fma2(hp3, w2p0, a[3][0]);  a[3][1] = fma2(hp3, w2p1, a[3][1]);
            u[0][0] = fma2(q0, mp0, u[0][0]);    u[0][1] = fma2(q0, mp1, u[0][1]);
            u[1][0] = fma2(q1, mp0, u[1][0]);    u[1][1] = fma2(q1, mp1, u[1][1]);
            u[2][0] = fma2(q2, mp0, u[2][0]);    u[2][1] = fma2(q2, mp1, u[2][1]);
            u[3][0] = fma2(q3, mp0, u[3][0]);    u[3][1] = fma2(q3, mp1, u[3][1]);
        }

        // epilogue for this j-tile
#pragma unroll
        for (int p = 0; p < 2; p++) {
            const int jA = j0 + 2 * p;
            const int jB = jA + 1;
            const float csA = css[jA], csB = css[jB];
            ull w3A[4], w3B[4];
#pragma unroll
            for (int dp = 0; dp < 4; dp++) {
                w3A[dp] = *(const ull*)&W3s[jA * DD + dp * 2];
                w3B[dp] = *(const ull*)&W3s[jB * DD + dp * 2];
            }
#pragma unroll
            for (int s = 0; s < 4; s++) {
                float2 av = unpack2(a[s][p]);
                float2 uv = unpack2(u[s][p]);
                float h2a = fast_tanh(av.x);
                float h2b = fast_tanh(av.y);
                float s2a = fmaf(-h2a, h2a, 1.0f);
                float s2b = fmaf(-h2b, h2b, 1.0f);
                tr[s] = fmaf(csA - uv.x, s2a, tr[s]);
                tr[s] = fmaf(csB - uv.y, s2b, tr[s]);
                ull ha = pack2(h2a, h2a);
                ull hb = pack2(h2b, h2b);
#pragma unroll
                for (int dp = 0; dp < 4; dp++) {
                    dzp[s][dp] = fma2(ha, w3A[dp], dzp[s][dp]);
                    dzp[s][dp] = fma2(hb, w3B[dp], dzp[s][dp]);
                }
            }
        }
    }

    // ---- butterfly reduce over the 8 jg lanes (xor 4, 8, 16) ----
#pragma unroll
    for (int off = 4; off <= 16; off <<= 1) {
#pragma unroll
        for (int s = 0; s < 4; s++) {
#pragma unroll
            for (int dp = 0; dp < 4; dp++)
                dzp[s][dp] = add2(dzp[s][dp], __shfl_xor_sync(0xffffffffu, dzp[s][dp], off));
            tr[s] += __shfl_xor_sync(0xffffffffu, tr[s], off);
        }
    }

    if (jg == 0) {
#pragma unroll
        for (int s = 0; s < 4; s++) {
            const int sample = blockIdx.x * SPB + sbase + s;
#pragma unroll
            for (int dp = 0; dp < 4; dp++) {
                float2 v = unpack2(dzp[s][dp]);
                float2 o = make_float2(v.x + b3s[2 * dp], v.y + b3s[2 * dp + 1]);
                *(float2*)&dz_out[(size_t)sample * DD + 2 * dp] = o;
            }
            dlogp_out[sample] = -tr[s];
        }
    }
}

extern "C" void kernel_launch(void* const* d_in, const int* in_sizes, int n_in,
                              void* d_out, int out_size) {
    const float* z  = (const float*)d_in[0];
    // d_in[1] = logp_z (unused: dlogp/dt = -trace only)
    const float* t  = (const float*)d_in[2];
    const float* W1 = (const float*)d_in[3];
    const float* b1 = (const float*)d_in[4];
    const float* W2 = (const float*)d_in[5];
    const float* b2 = (const float*)d_in[6];
    const float* W3 = (const float*)d_in[7];
    const float* b3 = (const float*)d_in[8];

    const int B = in_sizes[0] / DD;
    float* dz_out    = (float*)d_out;
    float* dlogp_out = dz_out + (size_t)B * DD;

    precompute_M_kernel<<<(HD * HD + 255) / 256, 256>>>(W1, W2, W3);

    cudaFuncSetAttribute(cnf_kernel,
                         cudaFuncAttributeMaxDynamicSharedMemorySize, SMEM_BYTES);
    cnf_kernel<<<(B + SPB - 1) / SPB, TPB, SMEM_BYTES>>>(
        z, t, W1, b1, b2, W3, b3, W2, dz_out, dlogp_out, B);
}

// round 5
// speedup vs baseline: 3.6739x; 1.7140x over previous
#include <cuda_runtime.h>
#include <cuda_bf16.h>
#include <cstdint>
#include <math.h>

#define HD 128
#define DD 8
#define TPB 256
#define SPB 128
#define APITCH 264        // bytes per A-tile row (132 bf16, padded vs 128 to dodge bank conflicts)

typedef unsigned long long ull;
typedef unsigned int uint;

// B operands in per-lane mma-fragment order: [jt][s][lane] x 4 bf16 (8B per lane entry)
__device__ __align__(16) __nv_bfloat16 g_bw2hi[16 * 8 * 32 * 4];
__device__ __align__(16) __nv_bfloat16 g_bw2lo[16 * 8 * 32 * 4];
__device__ __align__(16) __nv_bfloat16 g_bmhi[16 * 8 * 32 * 4];
__device__ __align__(16) __nv_bfloat16 g_bmlo[16 * 8 * 32 * 4];
__device__ float2 g_tab[1024];   // tanh table: {tanh(x_i), tanh(x_{i+1})-tanh(x_i)}

// ---------------- smem layout (bytes) ----------------
#define ATILE (128 * APITCH)                 // 33792
#define OFF_H1HI 0
#define OFF_H1LO (OFF_H1HI + ATILE)
#define OFF_S1HI (OFF_H1LO + ATILE)
#define OFF_S1LO (OFF_S1HI + ATILE)          // ends 135168
#define BSLICE   16384                       // 8 jt x 8 s x 32 lanes x 8B
#define OFF_BW2HI (OFF_S1LO + ATILE)
#define OFF_BW2LO (OFF_BW2HI + BSLICE)
#define OFF_BMHI  (OFF_BW2LO + BSLICE)
#define OFF_BMLO  (OFF_BMHI + BSLICE)        // ends 200704
#define OFF_TAB   (OFF_BMLO + BSLICE)        // 8192
#define OFF_W1    (OFF_TAB + 8192)           // 9*128*4 = 4608
#define OFF_W3    (OFF_W1 + 4608)            // 128*8*4 = 4096
#define OFF_B1    (OFF_W3 + 4096)            // 512
#define OFF_B2    (OFF_B1 + 512)             // 512
#define OFF_B3    (OFF_B2 + 512)             // 32 + pad
#define SMEM_BYTES (OFF_B3 + 64)

// ---------------- helpers ----------------
__device__ __forceinline__ float tanh_lut(const float2* tab, float x) {
    float xc = fminf(fmaxf(x, -4.995f), 4.995f);
    float f  = fmaf(xc, 102.4f, 512.0f);
    int   i  = (int)f;                 // f >= 0 -> trunc == floor
    float fr = f - (float)i;
    float2 e = tab[i];
    return fmaf(e.y, fr, e.x);
}
__device__ __forceinline__ ull pack2(float a, float b) {
    ull r; asm("mov.b64 %0, {%1,%2};" : "=l"(r) : "f"(a), "f"(b)); return r;
}
__device__ __forceinline__ float2 unpack2(ull v) {
    float2 f; asm("mov.b64 {%0,%1}, %2;" : "=f"(f.x), "=f"(f.y) : "l"(v)); return f;
}
__device__ __forceinline__ ull fma2(ull a, ull b, ull c) {
    ull r; asm("fma.rn.f32x2 %0, %1, %2, %3;" : "=l"(r) : "l"(a), "l"(b), "l"(c)); return r;
}
__device__ __forceinline__ ull add2(ull a, ull b) {
    ull r; asm("add.rn.f32x2 %0, %1, %2;" : "=l"(r) : "l"(a), "l"(b)); return r;
}
// split x0,x1 into bf16 hi/lo packed pairs (lo element = x0)
__device__ __forceinline__ void split_pack(float x0, float x1, uint& hi, uint& lo) {
    __nv_bfloat16 h0 = __float2bfloat16(x0);
    __nv_bfloat16 h1 = __float2bfloat16(x1);
    float r0 = x0 - __bfloat162float(h0);
    float r1 = x1 - __bfloat162float(h1);
    __nv_bfloat162 hp; hp.x = h0; hp.y = h1;
    __nv_bfloat162 lp; lp.x = __float2bfloat16(r0); lp.y = __float2bfloat16(r1);
    hi = *(uint*)&hp; lo = *(uint*)&lp;
}
__device__ __forceinline__ void mma_bf16(float* d, uint a0, uint a1, uint a2, uint a3,
                                         uint b0, uint b1) {
    asm("mma.sync.aligned.m16n8k16.row.col.f32.bf16.bf16.f32 "
        "{%0,%1,%2,%3},{%4,%5,%6,%7},{%8,%9},{%0,%1,%2,%3};"
        : "+f"(d[0]), "+f"(d[1]), "+f"(d[2]), "+f"(d[3])
        : "r"(a0), "r"(a1), "r"(a2), "r"(a3), "r"(b0), "r"(b1));
}

// one half-N (8 j-tiles) 3-chain split GEMM; acc[8][4] f32
__device__ __forceinline__ void gemm_half(const char* smp, int aHiOff, int aLoOff,
                                          int bHiOff, int bLoOff, int arow, int lane,
                                          float acc[8][4]) {
#pragma unroll
    for (int s = 0; s < 8; s++) {
        const char* pa = smp + aHiOff + arow + s * 32;
        const char* pl = smp + aLoOff + arow + s * 32;
        uint ah0 = *(const uint*)(pa);
        uint ah1 = *(const uint*)(pa + 8 * APITCH);
        uint ah2 = *(const uint*)(pa + 16);
        uint ah3 = *(const uint*)(pa + 8 * APITCH + 16);
        uint al0 = *(const uint*)(pl);
        uint al1 = *(const uint*)(pl + 8 * APITCH);
        uint al2 = *(const uint*)(pl + 16);
        uint al3 = *(const uint*)(pl + 8 * APITCH + 16);
#pragma unroll
        for (int q = 0; q < 8; q++) {
            const int bo = ((q * 8 + s) * 32 + lane) * 8;
            uint2 bh = *(const uint2*)(smp + bHiOff + bo);
            uint2 bl = *(const uint2*)(smp + bLoOff + bo);
            mma_bf16(acc[q], ah0, ah1, ah2, ah3, bh.x, bh.y);
            mma_bf16(acc[q], ah0, ah1, ah2, ah3, bl.x, bl.y);
            mma_bf16(acc[q], al0, al1, al2, al3, bh.x, bh.y);
        }
    }
}

// ---------------- precompute ----------------
__global__ void precompute_frags(const float* __restrict__ W1,
                                 const float* __restrict__ W2,
                                 const float* __restrict__ W3) {
    int idx = blockIdx.x * blockDim.x + threadIdx.x;   // 0..4095 = (jt, s, lane)
    if (idx >= 16 * 8 * 32) return;
    int lane = idx & 31, s = (idx >> 5) & 7, jt = idx >> 8;
    int g = lane >> 2, c = lane & 3;
    int j = jt * 8 + g;
    int kb = s * 16 + c * 2;
    int ks[4] = {kb, kb + 1, kb + 8, kb + 9};
#pragma unroll
    for (int e = 0; e < 4; e++) {
        int k = ks[e];
        float w2 = W2[k * HD + j];
        float cc = 0.0f;
#pragma unroll
        for (int d = 0; d < DD; d++) cc += W1[d * HD + k] * W3[j * DD + d];
        float m = w2 * cc;
        __nv_bfloat16 whi = __float2bfloat16(w2);
        __nv_bfloat16 mhi = __float2bfloat16(m);
        int o = idx * 4 + e;
        g_bw2hi[o] = whi;
        g_bw2lo[o] = __float2bfloat16(w2 - __bfloat162float(whi));
        g_bmhi[o]  = mhi;
        g_bmlo[o]  = __float2bfloat16(m - __bfloat162float(mhi));
    }
}

__global__ void build_table() {
    int i = blockIdx.x * blockDim.x + threadIdx.x;
    if (i >= 1024) return;
    float x0 = (float)(i - 512) * (1.0f / 102.4f);
    float x1 = (float)(i - 511) * (1.0f / 102.4f);
    float t0 = tanhf(x0), t1 = tanhf(x1);
    g_tab[i] = make_float2(t0, t1 - t0);
}

// ---------------- main kernel ----------------
__global__ __launch_bounds__(TPB, 1)
void cnf_mma_kernel(const float* __restrict__ z,
                    const float* __restrict__ t,
                    const float* __restrict__ W1, const float* __restrict__ b1,
                    const float* __restrict__ b2, const float* __restrict__ b3,
                    const float* __restrict__ W3,
                    float* __restrict__ dz_out, float* __restrict__ dlogp_out,
                    int B)
{
    extern __shared__ __align__(16) char sm[];
    const int tid = threadIdx.x;
    const int wid = tid >> 5;
    const int lane = tid & 31;
    const int g = lane >> 2;
    const int c = lane & 3;

    float*  W1s = (float*)(sm + OFF_W1);
    float*  W3s = (float*)(sm + OFF_W3);
    float*  b1s = (float*)(sm + OFF_B1);
    float*  b2s = (float*)(sm + OFF_B2);
    float*  b3s = (float*)(sm + OFF_B3);
    float2* tab = (float2*)(sm + OFF_TAB);

    // ---- stage misc + first B slice ----
    for (int i = tid; i < 1024; i += TPB) tab[i] = g_tab[i];
    for (int i = tid; i < 9 * HD; i += TPB) W1s[i] = W1[i];
    for (int i = tid; i < HD * DD; i += TPB) W3s[i] = W3[i];
    if (tid < HD) { b1s[tid] = b1[tid]; b2s[tid] = b2[tid]; }
    if (tid < DD) b3s[tid] = b3[tid];
    {
        uint4* d0 = (uint4*)(sm + OFF_BW2HI);
        uint4* d1 = (uint4*)(sm + OFF_BW2LO);
        uint4* d2 = (uint4*)(sm + OFF_BMHI);
        uint4* d3 = (uint4*)(sm + OFF_BMLO);
        const uint4* s0 = (const uint4*)g_bw2hi;
        const uint4* s1 = (const uint4*)g_bw2lo;
        const uint4* s2 = (const uint4*)g_bmhi;
        const uint4* s3 = (const uint4*)g_bmlo;
        for (int i = tid; i < 1024; i += TPB) {
            d0[i] = s0[i]; d1[i] = s1[i]; d2[i] = s2[i]; d3[i] = s3[i];
        }
    }
    __syncthreads();

    // ---- layer 1: thread computes 64 h1 values of one sample; writes h1 & s1 tiles ----
    {
        const int s_loc = tid & 127;
        const int k0 = (tid >> 7) * 64;
        const int sample0 = blockIdx.x * SPB + s_loc;
        float zr[DD];
        if (sample0 < B) {
            const float4* zv = (const float4*)(z + (size_t)sample0 * DD);
            float4 za = zv[0], zb = zv[1];
            zr[0]=za.x; zr[1]=za.y; zr[2]=za.z; zr[3]=za.w;
            zr[4]=zb.x; zr[5]=zb.y; zr[6]=zb.z; zr[7]=zb.w;
        } else {
#pragma unroll
            for (int d = 0; d < DD; d++) zr[d] = 0.0f;
        }
        const float tv = t[0];
        float h[64];
#pragma unroll
        for (int kk = 0; kk < 64; kk += 4) {
            float4 acc = *(const float4*)&b1s[k0 + kk];
#pragma unroll
            for (int d = 0; d < DD; d++) {
                float4 w = *(const float4*)&W1s[d * HD + k0 + kk];
                acc.x = fmaf(zr[d], w.x, acc.x);
                acc.y = fmaf(zr[d], w.y, acc.y);
                acc.z = fmaf(zr[d], w.z, acc.z);
                acc.w = fmaf(zr[d], w.w, acc.w);
            }
            float4 w8 = *(const float4*)&W1s[8 * HD + k0 + kk];
            h[kk + 0] = tanh_lut(tab, fmaf(tv, w8.x, acc.x));
            h[kk + 1] = tanh_lut(tab, fmaf(tv, w8.y, acc.y));
            h[kk + 2] = tanh_lut(tab, fmaf(tv, w8.z, acc.z));
            h[kk + 3] = tanh_lut(tab, fmaf(tv, w8.w, acc.w));
        }
        char* rowp = sm + s_loc * APITCH + k0 * 2;
#pragma unroll
        for (int p = 0; p < 32; p++) {
            float x0 = h[2 * p], x1 = h[2 * p + 1];
            uint hi, lo;
            split_pack(x0, x1, hi, lo);
            *(uint*)(rowp + OFF_H1HI + p * 4) = hi;
            *(uint*)(rowp + OFF_H1LO + p * 4) = lo;
            float s0 = fmaf(-x0, x0, 1.0f);
            float s1v = fmaf(-x1, x1, 1.0f);
            split_pack(s0, s1v, hi, lo);
            *(uint*)(rowp + OFF_S1HI + p * 4) = hi;
            *(uint*)(rowp + OFF_S1LO + p * 4) = lo;
        }
    }
    __syncthreads();

    // ---- GEMMs + epilogue, N in two halves ----
    const int arow = (wid * 16 + g) * APITCH + c * 4;
    ull dzg[4] = {0,0,0,0}, dzh[4] = {0,0,0,0};
    float trg = 0.0f, trh = 0.0f;

#pragma unroll 1
    for (int nh = 0; nh < 2; nh++) {
        if (nh == 1) {
            __syncthreads();
            // overwrite B region with second jt-slice
            uint4* d0 = (uint4*)(sm + OFF_BW2HI);
            uint4* d1 = (uint4*)(sm + OFF_BW2LO);
            uint4* d2 = (uint4*)(sm + OFF_BMHI);
            uint4* d3 = (uint4*)(sm + OFF_BMLO);
            const uint4* s0 = (const uint4*)g_bw2hi + 1024;
            const uint4* s1 = (const uint4*)g_bw2lo + 1024;
            const uint4* s2 = (const uint4*)g_bmhi + 1024;
            const uint4* s3 = (const uint4*)g_bmlo + 1024;
            for (int i = tid; i < 1024; i += TPB) {
                d0[i] = s0[i]; d1[i] = s1[i]; d2[i] = s2[i]; d3[i] = s3[i];
            }
            __syncthreads();
        }

        float acc1[8][4], acc2[8][4];
#pragma unroll
        for (int q = 0; q < 8; q++)
#pragma unroll
            for (int e = 0; e < 4; e++) { acc1[q][e] = 0.0f; acc2[q][e] = 0.0f; }

        gemm_half(sm, OFF_H1HI, OFF_H1LO, OFF_BW2HI, OFF_BW2LO, arow, lane, acc1);
        gemm_half(sm, OFF_S1HI, OFF_S1LO, OFF_BMHI,  OFF_BMLO,  arow, lane, acc2);

        // epilogue: h2 = tanh(a2 + b2); dz += h2*W3; trace += u*(1-h2^2)
#pragma unroll
        for (int q = 0; q < 8; q++) {
            const int j0 = (nh * 8 + q) * 8 + 2 * c;
            const float b2x = b2s[j0], b2y = b2s[j0 + 1];
            const ull* w30 = (const ull*)(W3s + j0 * DD);
            const ull* w31 = (const ull*)(W3s + (j0 + 1) * DD);
            {
                float h2 = tanh_lut(tab, acc1[q][0] + b2x);
                trg = fmaf(acc2[q][0], fmaf(-h2, h2, 1.0f), trg);
                ull hp = pack2(h2, h2);
                dzg[0] = fma2(hp, w30[0], dzg[0]); dzg[1] = fma2(hp, w30[1], dzg[1]);
                dzg[2] = fma2(hp, w30[2], dzg[2]); dzg[3] = fma2(hp, w30[3], dzg[3]);
            }
            {
                float h2 = tanh_lut(tab, acc1[q][1] + b2y);
                trg = fmaf(acc2[q][1], fmaf(-h2, h2, 1.0f), trg);
                ull hp = pack2(h2, h2);
                dzg[0] = fma2(hp, w31[0], dzg[0]); dzg[1] = fma2(hp, w31[1], dzg[1]);
                dzg[2] = fma2(hp, w31[2], dzg[2]); dzg[3] = fma2(hp, w31[3], dzg[3]);
            }
            {
                float h2 = tanh_lut(tab, acc1[q][2] + b2x);
                trh = fmaf(acc2[q][2], fmaf(-h2, h2, 1.0f), trh);
                ull hp = pack2(h2, h2);
                dzh[0] = fma2(hp, w30[0], dzh[0]); dzh[1] = fma2(hp, w30[1], dzh[1]);
                dzh[2] = fma2(hp, w30[2], dzh[2]); dzh[3] = fma2(hp, w30[3], dzh[3]);
            }
            {
                float h2 = tanh_lut(tab, acc1[q][3] + b2y);
                trh = fmaf(acc2[q][3], fmaf(-h2, h2, 1.0f), trh);
                ull hp = pack2(h2, h2);
                dzh[0] = fma2(hp, w31[0], dzh[0]); dzh[1] = fma2(hp, w31[1], dzh[1]);
                dzh[2] = fma2(hp, w31[2], dzh[2]); dzh[3] = fma2(hp, w31[3], dzh[3]);
            }
        }
    }

    // ---- reduce over the 4 c-lanes of each row group ----
#pragma unroll
    for (int off = 1; off <= 2; off <<= 1) {
        trg += __shfl_xor_sync(0xffffffffu, trg, off);
        trh += __shfl_xor_sync(0xffffffffu, trh, off);
#pragma unroll
        for (int e = 0; e < 4; e++) {
            dzg[e] = add2(dzg[e], __shfl_xor_sync(0xffffffffu, dzg[e], off));
            dzh[e] = add2(dzh[e], __shfl_xor_sync(0xffffffffu, dzh[e], off));
        }
    }

    if (c == 0) {
        const int sg = blockIdx.x * SPB + wid * 16 + g;
        const int sh = sg + 8;
        float4 b3a = *(const float4*)&b3s[0];
        float4 b3b = *(const float4*)&b3s[4];
        if (sg < B) {
            float2 v0 = unpack2(dzg[0]), v1 = unpack2(dzg[1]);
            float2 v2 = unpack2(dzg[2]), v3 = unpack2(dzg[3]);
            float4* ov = (float4*)(dz_out + (size_t)sg * DD);
            ov[0] = make_float4(v0.x + b3a.x, v0.y + b3a.y, v1.x + b3a.z, v1.y + b3a.w);
            ov[1] = make_float4(v2.x + b3b.x, v2.y + b3b.y, v3.x + b3b.z, v3.y + b3b.w);
            dlogp_out[sg] = -trg;
        }
        if (sh < B) {
            float2 v0 = unpack2(dzh[0]), v1 = unpack2(dzh[1]);
            float2 v2 = unpack2(dzh[2]), v3 = unpack2(dzh[3]);
            float4* ov = (float4*)(dz_out + (size_t)sh * DD);
            ov[0] = make_float4(v0.x + b3a.x, v0.y + b3a.y, v1.x + b3a.z, v1.y + b3a.w);
            ov[1] = make_float4(v2.x + b3b.x, v2.y + b3b.y, v3.x + b3b.z, v3.y + b3b.w);
            dlogp_out[sh] = -trh;
        }
    }
}

extern "C" void kernel_launch(void* const* d_in, const int* in_sizes, int n_in,
                              void* d_out, int out_size) {
    const float* z  = (const float*)d_in[0];
    // d_in[1] = logp_z (unused: dlogp/dt = -trace only)
    const float* t  = (const float*)d_in[2];
    const float* W1 = (const float*)d_in[3];
    const float* b1 = (const float*)d_in[4];
    const float* W2 = (const float*)d_in[5];
    const float* b2 = (const float*)d_in[6];
    const float* W3 = (const float*)d_in[7];
    const float* b3 = (const float*)d_in[8];

    const int B = in_sizes[0] / DD;
    float* dz_out    = (float*)d_out;
    float* dlogp_out = dz_out + (size_t)B * DD;

    build_table<<<4, 256>>>();
    precompute_frags<<<16, 256>>>(W1, W2, W3);

    cudaFuncSetAttribute(cnf_mma_kernel,
                         cudaFuncAttributeMaxDynamicSharedMemorySize, SMEM_BYTES);
    cnf_mma_kernel<<<(B + SPB - 1) / SPB, TPB, SMEM_BYTES>>>(
        z, t, W1, b1, b2, b3, W3, dz_out, dlogp_out, B);
}